// round 15
// baseline (speedup 1.0000x reference)
#include <cuda_runtime.h>

#define Nn 128
#define Tn 2048
#define Bn 64

// Split-scan scratch + combine rendezvous.
__device__ __align__(16) float g_alpha[2 * Bn][Nn];
__device__ __align__(16) float g_wvec[2 * Bn][Nn];
__device__ int g_sexpF[2 * Bn];
__device__ int g_sexpB[2 * Bn];
__device__ unsigned int g_cnt[Bn];   // monotonic across launches; (old&3)==3 = group finisher

__device__ __forceinline__ unsigned long long ffma2(unsigned long long a,
                                                    unsigned long long b,
                                                    unsigned long long c)
{
    unsigned long long d;
    asm("fma.rn.f32x2 %0, %1, %2, %3;" : "=l"(d) : "l"(a), "l"(b), "l"(c));
    return d;
}

__device__ __forceinline__ unsigned long long addf2(unsigned long long a,
                                                    unsigned long long b)
{
    unsigned long long d;
    asm("add.rn.f32x2 %0, %1, %2;" : "=l"(d) : "l"(a), "l"(b));
    return d;
}

__device__ __forceinline__ float unpack_add(unsigned long long a)
{
    float lo, hi;
    asm("mov.b64 {%0, %1}, %2;" : "=f"(lo), "=f"(hi) : "l"(a));
    return lo + hi;
}

__device__ __forceinline__ unsigned long long packf2(float a, float b)
{
    unsigned long long r;
    asm("mov.b64 %0, {%1, %2};" : "=l"(r) : "f"(a), "f"(b));
    return r;
}

// 128-dim dot: this thread's E column/row (regs) x broadcast vector (smem).
__device__ __forceinline__ float matvec128(const float* __restrict__ Ub,
                                           const ulonglong2* __restrict__ Ep)
{
    const ulonglong2* uvec = (const ulonglong2*)Ub;
    unsigned long long a0 = 0ull, a1 = 0ull, a2 = 0ull, a3 = 0ull;
    unsigned long long a4 = 0ull, a5 = 0ull, a6 = 0ull, a7 = 0ull;
    #pragma unroll
    for (int k = 0; k < 32; k += 4) {
        ulonglong2 u0 = uvec[k];
        ulonglong2 u1 = uvec[k + 1];
        ulonglong2 u2 = uvec[k + 2];
        ulonglong2 u3 = uvec[k + 3];
        a0 = ffma2(Ep[k].x,     u0.x, a0);
        a1 = ffma2(Ep[k].y,     u0.y, a1);
        a2 = ffma2(Ep[k + 1].x, u1.x, a2);
        a3 = ffma2(Ep[k + 1].y, u1.y, a3);
        a4 = ffma2(Ep[k + 2].x, u2.x, a4);
        a5 = ffma2(Ep[k + 2].y, u2.y, a5);
        a6 = ffma2(Ep[k + 3].x, u3.x, a6);
        a7 = ffma2(Ep[k + 3].y, u3.y, a7);
    }
    a0 = addf2(a0, a1); a2 = addf2(a2, a3);
    a4 = addf2(a4, a5); a6 = addf2(a6, a7);
    a0 = addf2(a0, a2); a4 = addf2(a4, a6);
    a0 = addf2(a0, a4);
    return unpack_add(a0);
}

// Forward step (no exit branch: the forward loop is exactly counted).
// MODE: 0 plain, 1 apply pending scale, 2 compute new block max.
#define FSTEP(TSTEP, EMV, TGV, RB, WB, MODE)                                    \
    {                                                                           \
        float p = __expf(EMV);                                                  \
        if (sup && (TGV) == 0) p = 0.0f;                                        \
        const int tp = (TSTEP) + 4;                                             \
        if (tp < Tn) { EMV = emrow[tp * Nn]; TGV = tgrow[tp * Nn]; }            \
        if ((MODE) == 1) { p *= inv_pend; Sexp += e_pend; }                     \
        float s = matvec128(U[RB], Ep);                                         \
        v = s * p;                                                              \
        U[WB][j] = v;                                                           \
        if ((MODE) == 2) {                                                      \
            unsigned int wmu = __reduce_max_sync(0xffffffffu, __float_as_uint(v)); \
            if (lane == 0) wmaxbuf[warp] = wmu;                                 \
        }                                                                       \
        __syncthreads();                                                        \
        if ((MODE) == 2) {                                                      \
            unsigned int rm = max(max(wmaxbuf[0], wmaxbuf[1]),                  \
                                  max(wmaxbuf[2], wmaxbuf[3]));                 \
            e_pend = (int)(rm >> 23) - 127;                                     \
            inv_pend = __int_as_float((127 - e_pend) << 23);                    \
        }                                                                       \
    }

// Backward step: w_{t-1} = E (p_t o w_t). Keeps the per-step exit check.
#define BSTEP(TSTEP, EMV, TGV, WB, MODE)                                        \
    {                                                                           \
        float p = __expf(EMV);                                                  \
        if (sup && (TGV) == 0) p = 0.0f;                                        \
        const int tp = (TSTEP) - 4;                                             \
        if (tp >= 0) { EMV = emrow[tp * Nn]; TGV = tgrow[tp * Nn]; }            \
        U[WB][j] = p * v;                                                       \
        __syncthreads();                                                        \
        if ((MODE) == 1) {                                                      \
            unsigned int rm = max(max(wmaxbuf[0], wmaxbuf[1]),                  \
                                  max(wmaxbuf[2], wmaxbuf[3]));                 \
            e_pend = (int)(rm >> 23) - 127;                                     \
            inv_pend = __int_as_float((127 - e_pend) << 23);                    \
            float s = matvec128(U[WB], Ep);                                     \
            v = s * inv_pend;                                                   \
            Sexp += e_pend;                                                     \
        } else {                                                                \
            v = matvec128(U[WB], Ep);                                           \
        }                                                                       \
        if ((MODE) == 2) {                                                      \
            unsigned int wmu = __reduce_max_sync(0xffffffffu, __float_as_uint(v)); \
            if (lane == 0) wmaxbuf[warp] = wmu;                                 \
        }                                                                       \
        if ((TSTEP) == m) goto fin_b;                                           \
    }

__global__ void __launch_bounds__(128, 2)
crf_scan_kernel(const float* __restrict__ em,
                const int* __restrict__ mask,
                const int* __restrict__ tgt,
                const float* __restrict__ trans,
                const float* __restrict__ st,
                const float* __restrict__ en,
                const int* __restrict__ ftr,
                const int* __restrict__ fst,
                const int* __restrict__ fen,
                float* __restrict__ out)
{
    __shared__ __align__(16) float U[2][Nn];
    __shared__ unsigned int wmaxbuf[4];
    __shared__ int s_len;
    __shared__ unsigned int s_go;

    const int tid = threadIdx.x;
    const int bidx = blockIdx.x;        // 256 blocks: (seq-channel) x (dir)
    const int dir = bidx & 1;           // 0 fwd, 1 bwd
    const int sc = bidx >> 1;
    const int c = sc & 1;               // 0 supervised, 1 partition
    const int b = sc >> 1;
    const int j = tid;
    const int warp = tid >> 5;
    const int lane = tid & 31;
    const bool sup = (c == 0);

    // ---- sequence length from mask ----
    if (tid == 0) s_len = 0;
    __syncthreads();
    {
        int cnt = 0;
        const int* mrow = mask + b * Tn;
        for (int k = tid; k < Tn; k += 128) cnt += (mrow[k] != 0) ? 1 : 0;
        #pragma unroll
        for (int o = 16; o; o >>= 1) cnt += __shfl_xor_sync(0xffffffffu, cnt, o);
        if (lane == 0) atomicAdd(&s_len, cnt);
    }

    // ---- E operand computed in-block (prep kernel folded in) ----
    // fwd: column j of exp(trans) (strided, coalesced across threads);
    // bwd: row j of exp(trans) (contiguous, vectorized).
    ulonglong2 Ep[32];
    if (dir == 0) {
        #pragma unroll
        for (int k = 0; k < 32; k++) {
            const int i0 = 4 * k;
            float x0 = trans[(i0 + 0) * Nn + j];
            float x1 = trans[(i0 + 1) * Nn + j];
            float x2 = trans[(i0 + 2) * Nn + j];
            float x3 = trans[(i0 + 3) * Nn + j];
            int f0 = ftr[(i0 + 0) * Nn + j];
            int f1 = ftr[(i0 + 1) * Nn + j];
            int f2 = ftr[(i0 + 2) * Nn + j];
            int f3 = ftr[(i0 + 3) * Nn + j];
            float e0 = f0 ? 0.0f : __expf(x0);
            float e1 = f1 ? 0.0f : __expf(x1);
            float e2 = f2 ? 0.0f : __expf(x2);
            float e3 = f3 ? 0.0f : __expf(x3);
            Ep[k].x = packf2(e0, e1);
            Ep[k].y = packf2(e2, e3);
        }
    } else {
        #pragma unroll
        for (int k = 0; k < 32; k++) {
            float4 x4 = *(const float4*)(trans + j * Nn + 4 * k);
            int4   f4 = *(const int4*)(ftr + j * Nn + 4 * k);
            float e0 = f4.x ? 0.0f : __expf(x4.x);
            float e1 = f4.y ? 0.0f : __expf(x4.y);
            float e2 = f4.z ? 0.0f : __expf(x4.z);
            float e3 = f4.w ? 0.0f : __expf(x4.w);
            Ep[k].x = packf2(e0, e1);
            Ep[k].y = packf2(e2, e3);
        }
    }
    const float stj = fst[j] ? 0.0f : __expf(st[j]);
    const float enj = fen[j] ? 0.0f : __expf(en[j]);

    const float* emrow = em + (b * Tn) * Nn + j;
    const int*   tgrow = tgt + (b * Tn) * Nn + j;

    __syncthreads();
    int L = s_len;
    if (L < 1) L = 1;
    if (L > Tn) L = Tn;
    // Split point aligned so tendF = m-1 is a multiple of 4 (counted fwd loop).
    const int m = (((L >> 1) & ~3) | 1);
    const int tendF = m - 1;

    float v;
    int Sexp = 0;
    int e_pend = 0;
    float inv_pend = 1.0f;

    if (dir == 0) {
        // ================= FORWARD: alpha_{m-1} =================
        {
            float p = __expf(emrow[0]);
            if (sup && tgrow[0] == 0) p = 0.0f;
            v = p * stj;
            U[0][j] = v;
            unsigned int wmu = __reduce_max_sync(0xffffffffu, __float_as_uint(v));
            if (lane == 0) wmaxbuf[warp] = wmu;
            __syncthreads();
            unsigned int rm = max(max(wmaxbuf[0], wmaxbuf[1]),
                                  max(wmaxbuf[2], wmaxbuf[3]));
            e_pend = (int)(rm >> 23) - 127;
            inv_pend = __int_as_float((127 - e_pend) << 23);
        }
        if (tendF > 0) {
            float em0, em1, em2, em3;
            int tg0, tg1, tg2, tg3;
            em0 = emrow[1 * Nn]; tg0 = tgrow[1 * Nn];
            em1 = emrow[2 * Nn]; tg1 = tgrow[2 * Nn];
            em2 = emrow[3 * Nn]; tg2 = tgrow[3 * Nn];
            em3 = emrow[4 * Nn]; tg3 = tgrow[4 * Nn];
            // Exactly counted: covers t = 1 .. tendF (tendF % 4 == 0).
            for (int base = 1; base + 3 <= tendF; base += 4) {
                FSTEP(base + 0, em0, tg0, 0, 1, 1)
                FSTEP(base + 1, em1, tg1, 1, 0, 0)
                FSTEP(base + 2, em2, tg2, 0, 1, 0)
                FSTEP(base + 3, em3, tg3, 1, 0, 2)
            }
        }
        g_alpha[sc][j] = v;
        if (tid == 0) g_sexpF[sc] = Sexp;
    } else {
        // ================= BACKWARD: w_{m-1} =================
        v = enj;
        {
            unsigned int wmu = __reduce_max_sync(0xffffffffu, __float_as_uint(v));
            if (lane == 0) wmaxbuf[warp] = wmu;   // published by first BSTEP's bar
        }
        if (L - 1 < m) goto fin_b;
        {
            const int t0i = L - 1;
            int i1 = t0i - 1 >= 0 ? t0i - 1 : 0;
            int i2 = t0i - 2 >= 0 ? t0i - 2 : 0;
            int i3 = t0i - 3 >= 0 ? t0i - 3 : 0;
            float em0, em1, em2, em3;
            int tg0, tg1, tg2, tg3;
            em0 = emrow[t0i * Nn]; tg0 = tgrow[t0i * Nn];
            em1 = emrow[i1 * Nn];  tg1 = tgrow[i1 * Nn];
            em2 = emrow[i2 * Nn];  tg2 = tgrow[i2 * Nn];
            em3 = emrow[i3 * Nn];  tg3 = tgrow[i3 * Nn];
            for (int t0 = t0i; t0 >= 1; t0 -= 4) {
                BSTEP(t0 - 0, em0, tg0, 0, 1)
                BSTEP(t0 - 1, em1, tg1, 1, 0)
                BSTEP(t0 - 2, em2, tg2, 0, 0)
                BSTEP(t0 - 3, em3, tg3, 1, 2)
            }
        }
fin_b:
        g_wvec[sc][j] = v;
        if (tid == 0) g_sexpB[sc] = Sexp;
    }

    // ================= COMBINE (folded): 4th arriver of this b's group =================
    // z_c = (SexpF+SexpB)*ln2 + log(alpha . w);  loss[b] = z_part - z_sup.
    if (tid == 0) {
        __threadfence();                               // release this block's results
        unsigned int old = atomicAdd(&g_cnt[b], 1u);   // monotonic across graph replays
        s_go = ((old & 3u) == 3u) ? 1u : 0u;
        if (s_go) __threadfence();                     // acquire the other 3 blocks' results
    }
    __syncthreads();
    if (s_go && warp == 0) {
        const int scA = (b << 1);
        const int scB = scA | 1;
        float dA = 0.0f, dB = 0.0f;
        #pragma unroll
        for (int q = 0; q < 4; q++) {
            int jj = lane + (q << 5);
            dA += g_alpha[scA][jj] * g_wvec[scA][jj];
            dB += g_alpha[scB][jj] * g_wvec[scB][jj];
        }
        #pragma unroll
        for (int o = 16; o; o >>= 1) {
            dA += __shfl_xor_sync(0xffffffffu, dA, o);
            dB += __shfl_xor_sync(0xffffffffu, dB, o);
        }
        if (lane == 0) {
            double zA = (double)(g_sexpF[scA] + g_sexpB[scA]) * 0.6931471805599453
                      + (double)logf(dA);
            double zB = (double)(g_sexpF[scB] + g_sexpB[scB]) * 0.6931471805599453
                      + (double)logf(dB);
            out[b] = (float)(zB - zA);
        }
    }
}

#undef FSTEP
#undef BSTEP

extern "C" void kernel_launch(void* const* d_in, const int* in_sizes, int n_in,
                              void* d_out, int out_size)
{
    const float* em    = (const float*)d_in[0];
    const int*   mask  = (const int*)d_in[1];
    const int*   tgt   = (const int*)d_in[2];
    const float* trans = (const float*)d_in[3];
    const float* st    = (const float*)d_in[4];
    const float* en    = (const float*)d_in[5];
    const int*   ftr   = (const int*)d_in[6];
    const int*   fst   = (const int*)d_in[7];
    const int*   fen   = (const int*)d_in[8];
    float* out = (float*)d_out;

    crf_scan_kernel<<<4 * Bn, 128>>>(em, mask, tgt, trans, st, en,
                                     ftr, fst, fen, out);
}

// round 16
// speedup vs baseline: 1.0143x; 1.0143x over previous
#include <cuda_runtime.h>

#define Nn 128
#define Tn 2048
#define Bn 64

// Precomputed exp-domain constants (written by prep_kernel each launch).
__device__ __align__(16) float g_ET[Nn * Nn];  // ET[j*N+i] (col-major: fwd)
__device__ __align__(16) float g_E[Nn * Nn];   // E[i*N+j]  (row-major: bwd)
__device__ float g_stexp[Nn];
__device__ float g_enexp[Nn];

// Split-scan scratch.
__device__ __align__(16) float g_alpha[2 * Bn][Nn];
__device__ __align__(16) float g_wvec[2 * Bn][Nn];
__device__ int g_sexpF[2 * Bn];
__device__ int g_sexpB[2 * Bn];

__global__ void prep_kernel(const float* __restrict__ trans,
                            const float* __restrict__ st,
                            const float* __restrict__ en,
                            const int* __restrict__ ftr,
                            const int* __restrict__ fst,
                            const int* __restrict__ fen)
{
    int idx = blockIdx.x * blockDim.x + threadIdx.x;
    if (idx < Nn * Nn) {
        int i = idx >> 7;
        int j = idx & (Nn - 1);
        float x = ftr[idx] ? 0.0f : expf(trans[idx]);
        g_E[idx] = x;
        g_ET[j * Nn + i] = x;
    }
    if (idx < Nn) {
        g_stexp[idx] = fst[idx] ? 0.0f : expf(st[idx]);
        g_enexp[idx] = fen[idx] ? 0.0f : expf(en[idx]);
    }
}

__device__ __forceinline__ unsigned long long ffma2(unsigned long long a,
                                                    unsigned long long b,
                                                    unsigned long long c)
{
    unsigned long long d;
    asm("fma.rn.f32x2 %0, %1, %2, %3;" : "=l"(d) : "l"(a), "l"(b), "l"(c));
    return d;
}

__device__ __forceinline__ unsigned long long addf2(unsigned long long a,
                                                    unsigned long long b)
{
    unsigned long long d;
    asm("add.rn.f32x2 %0, %1, %2;" : "=l"(d) : "l"(a), "l"(b));
    return d;
}

__device__ __forceinline__ float unpack_add(unsigned long long a)
{
    float lo, hi;
    asm("mov.b64 {%0, %1}, %2;" : "=f"(lo), "=f"(hi) : "l"(a));
    return lo + hi;
}

// 128-dim dot: this thread's E column/row (regs) x broadcast vector (smem).
__device__ __forceinline__ float matvec128(const float* __restrict__ Ub,
                                           const ulonglong2* __restrict__ Ep)
{
    const ulonglong2* uvec = (const ulonglong2*)Ub;
    unsigned long long a0 = 0ull, a1 = 0ull, a2 = 0ull, a3 = 0ull;
    unsigned long long a4 = 0ull, a5 = 0ull, a6 = 0ull, a7 = 0ull;
    #pragma unroll
    for (int k = 0; k < 32; k += 4) {
        ulonglong2 u0 = uvec[k];
        ulonglong2 u1 = uvec[k + 1];
        ulonglong2 u2 = uvec[k + 2];
        ulonglong2 u3 = uvec[k + 3];
        a0 = ffma2(Ep[k].x,     u0.x, a0);
        a1 = ffma2(Ep[k].y,     u0.y, a1);
        a2 = ffma2(Ep[k + 1].x, u1.x, a2);
        a3 = ffma2(Ep[k + 1].y, u1.y, a3);
        a4 = ffma2(Ep[k + 2].x, u2.x, a4);
        a5 = ffma2(Ep[k + 2].y, u2.y, a5);
        a6 = ffma2(Ep[k + 3].x, u3.x, a6);
        a7 = ffma2(Ep[k + 3].y, u3.y, a7);
    }
    a0 = addf2(a0, a1); a2 = addf2(a2, a3);
    a4 = addf2(a4, a5); a6 = addf2(a6, a7);
    a0 = addf2(a0, a2); a4 = addf2(a4, a6);
    a0 = addf2(a0, a4);
    return unpack_add(a0);
}

// Forward step (no exit branch: the forward loop is exactly counted).
// MODE: 0 plain, 1 apply pending scale, 2 compute new block max.
#define FSTEP(TSTEP, EMV, TGV, RB, WB, MODE)                                    \
    {                                                                           \
        float p = __expf(EMV);                                                  \
        if (sup && (TGV) == 0) p = 0.0f;                                        \
        const int tp = (TSTEP) + 4;                                             \
        if (tp < Tn) { EMV = emrow[tp * Nn]; TGV = tgrow[tp * Nn]; }            \
        if ((MODE) == 1) { p *= inv_pend; Sexp += e_pend; }                     \
        float s = matvec128(U[RB], Ep);                                         \
        v = s * p;                                                              \
        U[WB][j] = v;                                                           \
        if ((MODE) == 2) {                                                      \
            unsigned int wmu = __reduce_max_sync(0xffffffffu, __float_as_uint(v)); \
            if (lane == 0) wmaxbuf[warp] = wmu;                                 \
        }                                                                       \
        __syncthreads();                                                        \
        if ((MODE) == 2) {                                                      \
            unsigned int rm = max(max(wmaxbuf[0], wmaxbuf[1]),                  \
                                  max(wmaxbuf[2], wmaxbuf[3]));                 \
            e_pend = (int)(rm >> 23) - 127;                                     \
            inv_pend = __int_as_float((127 - e_pend) << 23);                    \
        }                                                                       \
    }

// Backward step: w_{t-1} = E (p_t o w_t). Keeps the per-step exit check.
#define BSTEP(TSTEP, EMV, TGV, WB, MODE)                                        \
    {                                                                           \
        float p = __expf(EMV);                                                  \
        if (sup && (TGV) == 0) p = 0.0f;                                        \
        const int tp = (TSTEP) - 4;                                             \
        if (tp >= 0) { EMV = emrow[tp * Nn]; TGV = tgrow[tp * Nn]; }            \
        U[WB][j] = p * v;                                                       \
        __syncthreads();                                                        \
        if ((MODE) == 1) {                                                      \
            unsigned int rm = max(max(wmaxbuf[0], wmaxbuf[1]),                  \
                                  max(wmaxbuf[2], wmaxbuf[3]));                 \
            e_pend = (int)(rm >> 23) - 127;                                     \
            inv_pend = __int_as_float((127 - e_pend) << 23);                    \
            float s = matvec128(U[WB], Ep);                                     \
            v = s * inv_pend;                                                   \
            Sexp += e_pend;                                                     \
        } else {                                                                \
            v = matvec128(U[WB], Ep);                                           \
        }                                                                       \
        if ((MODE) == 2) {                                                      \
            unsigned int wmu = __reduce_max_sync(0xffffffffu, __float_as_uint(v)); \
            if (lane == 0) wmaxbuf[warp] = wmu;                                 \
        }                                                                       \
        if ((TSTEP) == m) goto fin_b;                                           \
    }

__global__ void __launch_bounds__(128, 2)
crf_scan_kernel(const float* __restrict__ em,
                const int* __restrict__ mask,
                const int* __restrict__ tgt)
{
    __shared__ __align__(16) float U[2][Nn];
    __shared__ unsigned int wmaxbuf[4];
    __shared__ int s_len;

    const int tid = threadIdx.x;
    const int bidx = blockIdx.x;        // 256 blocks: (seq-channel) x (dir)
    const int dir = bidx & 1;           // 0 fwd, 1 bwd
    const int sc = bidx >> 1;
    const int c = sc & 1;               // 0 supervised, 1 partition
    const int b = sc >> 1;
    const int j = tid;
    const int warp = tid >> 5;
    const int lane = tid & 31;
    const bool sup = (c == 0);

    // ---- sequence length from mask ----
    if (tid == 0) s_len = 0;
    __syncthreads();
    {
        int cnt = 0;
        const int* mrow = mask + b * Tn;
        for (int k = tid; k < Tn; k += 128) cnt += (mrow[k] != 0) ? 1 : 0;
        #pragma unroll
        for (int o = 16; o; o >>= 1) cnt += __shfl_xor_sync(0xffffffffu, cnt, o);
        if (lane == 0) atomicAdd(&s_len, cnt);
    }

    // ---- E operand: contiguous 128-float run per thread ----
    ulonglong2 Ep[32];
    {
        const float* Emat = (dir == 0) ? g_ET : g_E;
        const ulonglong2* erow = (const ulonglong2*)(Emat + j * Nn);
        #pragma unroll
        for (int k = 0; k < 32; k++) Ep[k] = erow[k];
    }
    const float enj = g_enexp[j];
    const float stj = g_stexp[j];

    const float* emrow = em + (b * Tn) * Nn + j;
    const int*   tgrow = tgt + (b * Tn) * Nn + j;

    __syncthreads();
    int L = s_len;
    if (L < 1) L = 1;
    if (L > Tn) L = Tn;
    // Split point aligned so tendF = m-1 is a multiple of 4: the forward loop
    // is exactly counted and needs NO per-step exit branches.
    // m = ((L>>1) & ~3) | 1  =>  1 <= m <= L-1 for all L >= 2; m = 1 for L = 1.
    const int m = (((L >> 1) & ~3) | 1);
    const int tendF = m - 1;

    float v;
    int Sexp = 0;
    int e_pend = 0;
    float inv_pend = 1.0f;

    if (dir == 0) {
        // ================= FORWARD: alpha_{m-1} =================
        {
            float p = __expf(emrow[0]);
            if (sup && tgrow[0] == 0) p = 0.0f;
            v = p * stj;
            U[0][j] = v;
            unsigned int wmu = __reduce_max_sync(0xffffffffu, __float_as_uint(v));
            if (lane == 0) wmaxbuf[warp] = wmu;
            __syncthreads();
            unsigned int rm = max(max(wmaxbuf[0], wmaxbuf[1]),
                                  max(wmaxbuf[2], wmaxbuf[3]));
            e_pend = (int)(rm >> 23) - 127;
            inv_pend = __int_as_float((127 - e_pend) << 23);
        }
        if (tendF > 0) {
            float em0, em1, em2, em3;
            int tg0, tg1, tg2, tg3;
            em0 = emrow[1 * Nn]; tg0 = tgrow[1 * Nn];
            em1 = emrow[2 * Nn]; tg1 = tgrow[2 * Nn];
            em2 = emrow[3 * Nn]; tg2 = tgrow[3 * Nn];
            em3 = emrow[4 * Nn]; tg3 = tgrow[4 * Nn];
            // Exactly counted: covers t = 1 .. tendF (tendF % 4 == 0).
            for (int base = 1; base + 3 <= tendF; base += 4) {
                FSTEP(base + 0, em0, tg0, 0, 1, 1)
                FSTEP(base + 1, em1, tg1, 1, 0, 0)
                FSTEP(base + 2, em2, tg2, 0, 1, 0)
                FSTEP(base + 3, em3, tg3, 1, 0, 2)
            }
        }
        g_alpha[sc][j] = v;
        if (tid == 0) g_sexpF[sc] = Sexp;
    } else {
        // ================= BACKWARD: w_{m-1} =================
        v = enj;
        {
            unsigned int wmu = __reduce_max_sync(0xffffffffu, __float_as_uint(v));
            if (lane == 0) wmaxbuf[warp] = wmu;   // published by first BSTEP's bar
        }
        if (L - 1 < m) goto fin_b;
        {
            const int t0i = L - 1;
            int i1 = t0i - 1 >= 0 ? t0i - 1 : 0;
            int i2 = t0i - 2 >= 0 ? t0i - 2 : 0;
            int i3 = t0i - 3 >= 0 ? t0i - 3 : 0;
            float em0, em1, em2, em3;
            int tg0, tg1, tg2, tg3;
            em0 = emrow[t0i * Nn]; tg0 = tgrow[t0i * Nn];
            em1 = emrow[i1 * Nn];  tg1 = tgrow[i1 * Nn];
            em2 = emrow[i2 * Nn];  tg2 = tgrow[i2 * Nn];
            em3 = emrow[i3 * Nn];  tg3 = tgrow[i3 * Nn];
            for (int t0 = t0i; t0 >= 1; t0 -= 4) {
                BSTEP(t0 - 0, em0, tg0, 0, 1)
                BSTEP(t0 - 1, em1, tg1, 1, 0)
                BSTEP(t0 - 2, em2, tg2, 0, 0)
                BSTEP(t0 - 3, em3, tg3, 1, 2)
            }
        }
fin_b:
        g_wvec[sc][j] = v;
        if (tid == 0) g_sexpB[sc] = Sexp;
    }
}

#undef FSTEP
#undef BSTEP

// Combine: z_c = (SexpF+SexpB)*ln2 + log(alpha . w);  loss[b] = z_part - z_sup.
__global__ void combine_kernel(float* __restrict__ out)
{
    __shared__ float zpA[4], zpB[4];
    const int b = blockIdx.x;
    const int j = threadIdx.x;
    const int warp = j >> 5;
    const int lane = j & 31;
    const int scA = (b << 1);
    const int scB = scA | 1;

    float dA = g_alpha[scA][j] * g_wvec[scA][j];
    float dB = g_alpha[scB][j] * g_wvec[scB][j];
    #pragma unroll
    for (int o = 16; o; o >>= 1) {
        dA += __shfl_xor_sync(0xffffffffu, dA, o);
        dB += __shfl_xor_sync(0xffffffffu, dB, o);
    }
    if (lane == 0) { zpA[warp] = dA; zpB[warp] = dB; }
    __syncthreads();
    if (j == 0) {
        float sA = (zpA[0] + zpA[1]) + (zpA[2] + zpA[3]);
        float sB = (zpB[0] + zpB[1]) + (zpB[2] + zpB[3]);
        double zA = (double)(g_sexpF[scA] + g_sexpB[scA]) * 0.6931471805599453
                  + (double)logf(sA);
        double zB = (double)(g_sexpF[scB] + g_sexpB[scB]) * 0.6931471805599453
                  + (double)logf(sB);
        out[b] = (float)(zB - zA);
    }
}

extern "C" void kernel_launch(void* const* d_in, const int* in_sizes, int n_in,
                              void* d_out, int out_size)
{
    const float* em    = (const float*)d_in[0];
    const int*   mask  = (const int*)d_in[1];
    const int*   tgt   = (const int*)d_in[2];
    const float* trans = (const float*)d_in[3];
    const float* st    = (const float*)d_in[4];
    const float* en    = (const float*)d_in[5];
    const int*   ftr   = (const int*)d_in[6];
    const int*   fst   = (const int*)d_in[7];
    const int*   fen   = (const int*)d_in[8];
    float* out = (float*)d_out;

    prep_kernel<<<64, 256>>>(trans, st, en, ftr, fst, fen);
    crf_scan_kernel<<<4 * Bn, 128>>>(em, mask, tgt);
    combine_kernel<<<Bn, 128>>>(out);
}